// round 16
// baseline (speedup 1.0000x reference)
#include <cuda_runtime.h>

// Problem constants (UP=3, DOWN=2, Lh=63, Lb=51)
#define R_OUT 16                   // same-phase outputs per thread
#define BLOCK_T 96                 // ONE group: 3 warps (one per phase)
#define GT_OUT 1536                // outputs per block (3*32*16)
#define TILE_XG 1084               // logical floats per tile (need 1082, even)
#define XS_PHYS 1152               // >= XP(TILE_XG-1)+1
#define OS_PHYS 1568               // 1536 + 1536/48 + pad
#define NSTEP 29                   // packed coefficient steps (v in [2,60))

// xs swizzle: pad TWO floats per 32 -> lane logical stride 32 becomes phys
// stride 34 (2 mod 32 banks -> LDS.64 conflict-free), 8B alignment preserved.
// Window base 32*ll: XP(32*ll + e) = 34*ll + XPOFF(e).
#define XP(i)    ((i) + (((i) >> 5) << 1))
#define XPOFF(e) ((e) + (((e) >> 5) << 1))

__device__ __forceinline__ unsigned long long fma_f32x2(
    unsigned long long a, unsigned long long bb, unsigned long long c) {
    unsigned long long d;
    asm("fma.rn.f32x2 %0, %1, %2, %3;" : "=l"(d) : "l"(a), "l"(bb), "l"(c));
    return d;
}

// Exact two-stage value for edge outputs (head j<50 where u-padding matters,
// tail j>=n_out where appended zeros matter).
__device__ float edge_value(const float* __restrict__ x,
                            const float* __restrict__ h,
                            const float* __restrict__ b,
                            long long j, int n_in, long long n_out) {
    float acc = 0.0f;
    for (int s = 0; s < 51; s++) {
        long long k = j - s;
        if (k < 0 || k >= n_out) continue;
        long long mlo = (2 * k - 30 + 2) / 3;
        if (mlo < 0) mlo = 0;
        long long mhi = (2 * k + 32) / 3;
        if (mhi > (long long)n_in - 1) mhi = (long long)n_in - 1;
        float u = 0.0f;
        for (long long m = mlo; m <= mhi; m++) {
            long long hi = 2 * k + 32 - 3 * m;
            if (hi >= 0 && hi < 63) u = fmaf(x[m], h[hi], u);
        }
        acc = fmaf(b[s], u, acc);
    }
    return acc;
}

// Tiny-CTA fused kernel: one 96-thread group per block, 8192 blocks.
// out[j] = sum_m x[m]*C[2j+32-3m], C[r] = sum_s b[s]*h[r-2s] (r in [0,163)).
// Block T: j = 1536*T + g + 3*(16*ll + d), G0 = 1024*T - 46 (even).
// With i = m - G0 = 32*ll + 2d + v: out = sum_v xs_log[32ll+2d+v] * D_g[v],
// D_g[v] = C[2g + 170 - 3v] (zero outside [0,162]); v in [2,60), 29 steps.
__global__ void __launch_bounds__(BLOCK_T, 8) fused_kernel(
    const float* __restrict__ x, const float* __restrict__ h,
    const float* __restrict__ b, float* __restrict__ out,
    int n_in, int n_out, int out_total)
{
    __shared__ float xs[XS_PHYS];
    __shared__ float os[OS_PHYS];
    __shared__ unsigned long long cs[3][NSTEP];

    int tid = threadIdx.x;
    int T = blockIdx.x;
    int ntiles = gridDim.x;
    int G0 = (T << 10) - 46;       // even; global x index of logical xs[0]

    // --- tile fill issued FIRST (cp.async, interior blocks) so the
    //     coefficient FMA chain below hides the DRAM latency ---
    if (T != 0 && T != ntiles - 1) {
        const float2* src = (const float2*)(x + G0);
        #pragma unroll
        for (int q2 = tid; q2 < TILE_XG / 2; q2 += BLOCK_T) {
            unsigned dst = (unsigned)__cvta_generic_to_shared(&xs[XP(2 * q2)]);
            asm volatile("cp.async.ca.shared.global [%0], [%1], 8;\n"
                         :: "r"(dst), "l"(src + q2));
        }
        asm volatile("cp.async.commit_group;\n" ::: "memory");
    } else {
        #pragma unroll
        for (int q2 = tid; q2 < TILE_XG / 2; q2 += BLOCK_T) {
            int i0 = G0 + 2 * q2;
            float2 v;
            v.x = (i0 >= 0 && i0 < n_in) ? x[i0] : 0.0f;
            v.y = (i0 + 1 >= 0 && i0 + 1 < n_in) ? x[i0 + 1] : 0.0f;
            *(float2*)&xs[XP(2 * q2)] = v;
        }
        asm volatile("cp.async.commit_group;\n" ::: "memory");
    }

    // --- coefficient pairs, computed directly from h,b (overlaps the fill) ---
    // cs[g][t] = (D_g[2+2t], D_g[3+2t]) = (C[2g+164-6t], C[2g+161-6t])
    if (tid < 3 * NSTEP) {
        int gg = tid / NSTEP, t = tid % NSTEP;
        float hv[2];
        #pragma unroll
        for (int qq = 0; qq < 2; qq++) {
            int idx = 2 * gg + 164 - 6 * t - 3 * qq;   // C index
            float val = 0.0f;
            if (idx >= 0 && idx <= 162) {
                #pragma unroll
                for (int s = 0; s < 51; s++) {
                    int hh = idx - 2 * s;
                    if (hh >= 0 && hh < 63) val = fmaf(__ldg(&b[s]), __ldg(&h[hh]), val);
                }
            }
            hv[qq] = val;
        }
        cs[gg][t] =
            (unsigned long long)__float_as_uint(hv[0]) |
            ((unsigned long long)__float_as_uint(hv[1]) << 32);
    }

    asm volatile("cp.async.wait_group 0;\n" ::: "memory");
    __syncthreads();   // xs + cs ready (3-warp barrier: cheap)

    // --- main packed FIR loop ---
    int g = tid >> 5;              // phase 0..2 (one warp per phase)
    int ll = tid & 31;
    const float* xb = xs + 34 * ll;

    // circular packed window: slot k = {xs_log[32ll+2+2k], xs_log[32ll+3+2k]}
    unsigned long long w2[16];
    #pragma unroll
    for (int k = 0; k < 16; k++)
        w2[k] = *(const unsigned long long*)&xb[XPOFF(2 + 2 * k)];

    unsigned long long acc2[R_OUT];
    #pragma unroll
    for (int d = 0; d < R_OUT; d++) acc2[d] = 0ull;

    const unsigned long long* cp_ = cs[g];

    unsigned long long c_cur = cp_[0];
    #pragma unroll
    for (int t = 0; t < NSTEP; t++) {
        unsigned long long c_nxt = (t < NSTEP - 1) ? cp_[t + 1] : 0ull;
        #pragma unroll
        for (int d = 0; d < R_OUT; d++)
            acc2[d] = fma_f32x2(w2[(t + d) & 15], c_cur, acc2[d]);
        if (t < NSTEP - 1)
            w2[t & 15] = *(const unsigned long long*)&xb[XPOFF(2 + 2 * (t + 16))];
        c_cur = c_nxt;
    }

    // --- staging: logical oo = 48*ll + (g+3d), phys = oo + oo/48 = 49*ll + g + 3d ---
    #pragma unroll
    for (int d = 0; d < R_OUT; d++) {
        float lo = __uint_as_float((unsigned)(acc2[d] & 0xffffffffull));
        float hi = __uint_as_float((unsigned)(acc2[d] >> 32));
        os[49 * ll + g + 3 * d] = lo + hi;
    }
    __syncthreads();   // 3-warp barrier

    // --- coalesced float4 writeback (1536 outputs) ---
    int jgrp = T * GT_OUT;
    if (jgrp >= 50 && jgrp + GT_OUT <= n_out) {
        #pragma unroll
        for (int it = 0; it < 4; it++) {
            int q4 = 4 * tid + 384 * it;
            int ph = q4 + q4 / 48;
            float4 v;
            v.x = os[ph];
            v.y = os[ph + 1];
            v.z = os[ph + 2];
            v.w = os[ph + 3];
            *(float4*)&out[jgrp + q4] = v;
        }
    } else {
        for (int q = tid; q < GT_OUT; q += BLOCK_T) {
            int j = jgrp + q;
            // j >= 50 (head handled exactly below) and j < n_out
            if ((unsigned)(j - 50) < (unsigned)(n_out - 50)) out[j] = os[q + q / 48];
        }
    }

    // --- block 0: exact edge outputs (head + tail) ---
    if (T == 0) {
        int n_edge = 50 + (out_total - n_out);
        for (int q = tid; q < n_edge; q += BLOCK_T) {
            long long j = (q < 50) ? (long long)q
                                   : (long long)n_out + (q - 50);
            out[j] = edge_value(x, h, b, j, n_in, (long long)n_out);
        }
    }
}

extern "C" void kernel_launch(void* const* d_in, const int* in_sizes, int n_in_arrs,
                              void* d_out, int out_size) {
    const float* x = (const float*)d_in[0];
    const float* h = (const float*)d_in[1];
    const float* b = (const float*)d_in[2];
    float* out = (float*)d_out;

    int n_in = in_sizes[0];  // 8 * 1048576 = 8388608
    long long n3 = (long long)n_in * 3;
    long long n_out = n3 / 2 + ((n3 % 2) ? 1 : 0);  // 12582912
    int out_total = out_size;                        // 12583008
    int ntiles = (int)((n_out + GT_OUT - 1) / GT_OUT);  // 8192

    fused_kernel<<<ntiles, BLOCK_T>>>(x, h, b, out, n_in, (int)n_out, out_total);
}

// round 17
// speedup vs baseline: 1.0719x; 1.0719x over previous
#include <cuda_runtime.h>

// Problem constants (UP=3, DOWN=2, Lh=63, Lb=51)
#define R_OUT 16                   // same-phase outputs per thread
#define BLOCK_T 96                 // 3 warps (one per phase)
#define NS 2                       // subtiles per block
#define GT_OUT 1536                // outputs per subtile (3*32*16)
#define TILE_XG 1084               // logical floats per subtile (need 1082, even)
#define XS_PHYS 1152               // >= XP(TILE_XG-1)+1
#define OS_PHYS 1568               // 1536 + 1536/48 + pad
#define NSTEP 29                   // packed coefficient steps (v in [2,60))

// xs swizzle: pad TWO floats per 32 -> lane logical stride 32 becomes phys
// stride 34 (2 mod 32 banks -> LDS.64 conflict-free), 8B alignment preserved.
// Window base 32*ll: XP(32*ll + e) = 34*ll + XPOFF(e).
#define XP(i)    ((i) + (((i) >> 5) << 1))
#define XPOFF(e) ((e) + (((e) >> 5) << 1))

__device__ __forceinline__ unsigned long long fma_f32x2(
    unsigned long long a, unsigned long long bb, unsigned long long c) {
    unsigned long long d;
    asm("fma.rn.f32x2 %0, %1, %2, %3;" : "=l"(d) : "l"(a), "l"(bb), "l"(c));
    return d;
}

// Exact two-stage value for edge outputs (head j<50 where u-padding matters,
// tail j>=n_out where appended zeros matter).
__device__ float edge_value(const float* __restrict__ x,
                            const float* __restrict__ h,
                            const float* __restrict__ b,
                            long long j, int n_in, long long n_out) {
    float acc = 0.0f;
    for (int s = 0; s < 51; s++) {
        long long k = j - s;
        if (k < 0 || k >= n_out) continue;
        long long mlo = (2 * k - 30 + 2) / 3;
        if (mlo < 0) mlo = 0;
        long long mhi = (2 * k + 32) / 3;
        if (mhi > (long long)n_in - 1) mhi = (long long)n_in - 1;
        float u = 0.0f;
        for (long long m = mlo; m <= mhi; m++) {
            long long hi = 2 * k + 32 - 3 * m;
            if (hi >= 0 && hi < 63) u = fmaf(x[m], h[hi], u);
        }
        acc = fmaf(b[s], u, acc);
    }
    return acc;
}

// Subtile fill: cp.async (interior) or guarded direct stores (global first/
// last subtile). Caller commits the group afterwards.
__device__ __forceinline__ void fill_g(
    float* xs, const float* __restrict__ x,
    int TT, int nsub, int n_in, int tid)
{
    int G0 = (TT << 10) - 46;       // even; global x index of logical xs[0]
    if (TT != 0 && TT != nsub - 1) {
        const float2* src = (const float2*)(x + G0);
        #pragma unroll
        for (int q2 = tid; q2 < TILE_XG / 2; q2 += BLOCK_T) {
            unsigned dst = (unsigned)__cvta_generic_to_shared(&xs[XP(2 * q2)]);
            asm volatile("cp.async.ca.shared.global [%0], [%1], 8;\n"
                         :: "r"(dst), "l"(src + q2));
        }
    } else {
        #pragma unroll
        for (int q2 = tid; q2 < TILE_XG / 2; q2 += BLOCK_T) {
            int i0 = G0 + 2 * q2;
            float2 v;
            v.x = (i0 >= 0 && i0 < n_in) ? x[i0] : 0.0f;
            v.y = (i0 + 1 >= 0 && i0 + 1 < n_in) ? x[i0 + 1] : 0.0f;
            *(float2*)&xs[XP(2 * q2)] = v;
        }
    }
}

// 96-thread CTA, 2 pipelined subtiles per block, coeff built once per block.
// out[j] = sum_m x[m]*C[2j+32-3m], C[r] = sum_s b[s]*h[r-2s] (r in [0,163)).
// Subtile TT: j = 1536*TT + g + 3*(16*ll + d), G0 = 1024*TT - 46 (even).
// With i = m - G0 = 32*ll + 2d + v: out = sum_v xs_log[32ll+2d+v] * D_g[v],
// D_g[v] = C[2g + 170 - 3v] (zero outside [0,162]); v in [2,60), 29 steps.
__global__ void __launch_bounds__(BLOCK_T, 8) fused_kernel(
    const float* __restrict__ x, const float* __restrict__ h,
    const float* __restrict__ b, float* __restrict__ out,
    int n_in, int n_out, int out_total, int nsub)
{
    __shared__ float xsb[NS][XS_PHYS];
    __shared__ float os[OS_PHYS];
    __shared__ unsigned long long cs[3][NSTEP];

    int tid = threadIdx.x;
    int T0 = blockIdx.x * NS;

    // --- prefetch BOTH subtiles immediately (2-deep pipeline) ---
    fill_g(xsb[0], x, T0, nsub, n_in, tid);
    asm volatile("cp.async.commit_group;\n" ::: "memory");
    fill_g(xsb[1], x, T0 + 1, nsub, n_in, tid);
    asm volatile("cp.async.commit_group;\n" ::: "memory");

    // --- coefficient pairs, once per block (overlaps both fills) ---
    // cs[g][t] = (D_g[2+2t], D_g[3+2t]) = (C[2g+164-6t], C[2g+161-6t])
    if (tid < 3 * NSTEP) {
        int gg = tid / NSTEP, t = tid % NSTEP;
        float hv[2];
        #pragma unroll
        for (int qq = 0; qq < 2; qq++) {
            int idx = 2 * gg + 164 - 6 * t - 3 * qq;   // C index
            float val = 0.0f;
            if (idx >= 0 && idx <= 162) {
                #pragma unroll
                for (int s = 0; s < 51; s++) {
                    int hh = idx - 2 * s;
                    if (hh >= 0 && hh < 63) val = fmaf(__ldg(&b[s]), __ldg(&h[hh]), val);
                }
            }
            hv[qq] = val;
        }
        cs[gg][t] =
            (unsigned long long)__float_as_uint(hv[0]) |
            ((unsigned long long)__float_as_uint(hv[1]) << 32);
    }

    int g = tid >> 5;              // phase 0..2 (one warp per phase)
    int ll = tid & 31;
    const unsigned long long* cp_ = cs[g];

    #pragma unroll
    for (int s = 0; s < NS; s++) {
        // wait for subtile s's fill (leave later groups pending)
        if (s == 0) asm volatile("cp.async.wait_group 1;\n" ::: "memory");
        else        asm volatile("cp.async.wait_group 0;\n" ::: "memory");
        __syncthreads();   // 3-warp barrier: xs[s] + cs ready; also orders
                           // previous subtile's writeback reads before restage

        const float* xb = xsb[s] + 34 * ll;

        // circular packed window: slot k = {xs_log[32ll+2+2k], xs_log[32ll+3+2k]}
        unsigned long long w2[16];
        #pragma unroll
        for (int k = 0; k < 16; k++)
            w2[k] = *(const unsigned long long*)&xb[XPOFF(2 + 2 * k)];

        unsigned long long acc2[R_OUT];
        #pragma unroll
        for (int d = 0; d < R_OUT; d++) acc2[d] = 0ull;

        unsigned long long c_cur = cp_[0];
        #pragma unroll
        for (int t = 0; t < NSTEP; t++) {
            unsigned long long c_nxt = (t < NSTEP - 1) ? cp_[t + 1] : 0ull;
            #pragma unroll
            for (int d = 0; d < R_OUT; d++)
                acc2[d] = fma_f32x2(w2[(t + d) & 15], c_cur, acc2[d]);
            if (t < NSTEP - 1)
                w2[t & 15] = *(const unsigned long long*)&xb[XPOFF(2 + 2 * (t + 16))];
            c_cur = c_nxt;
        }

        // --- staging: logical oo = 48*ll + (g+3d), phys = 49*ll + g + 3d ---
        #pragma unroll
        for (int d = 0; d < R_OUT; d++) {
            float lo = __uint_as_float((unsigned)(acc2[d] & 0xffffffffull));
            float hi = __uint_as_float((unsigned)(acc2[d] >> 32));
            os[49 * ll + g + 3 * d] = lo + hi;
        }
        __syncthreads();   // 3-warp barrier

        // --- coalesced float4 writeback (1536 outputs; n_out = 1536*nsub exactly,
        //     so only the global head needs a guard) ---
        int TT = T0 + s;
        int jgrp = TT * GT_OUT;
        if (TT != 0) {
            #pragma unroll
            for (int it = 0; it < 4; it++) {
                int q4 = 4 * tid + 384 * it;
                int ph = q4 + q4 / 48;
                float4 v;
                v.x = os[ph];
                v.y = os[ph + 1];
                v.z = os[ph + 2];
                v.w = os[ph + 3];
                *(float4*)&out[jgrp + q4] = v;
            }
        } else {
            for (int q = tid; q < GT_OUT; q += BLOCK_T) {
                int j = jgrp + q;
                if (j >= 50) out[j] = os[q + q / 48];   // head j<50 handled below
            }
        }
    }

    // --- block 0: exact edge outputs (head + tail) ---
    if (blockIdx.x == 0) {
        int n_edge = 50 + (out_total - n_out);
        for (int q = tid; q < n_edge; q += BLOCK_T) {
            long long j = (q < 50) ? (long long)q
                                   : (long long)n_out + (q - 50);
            out[j] = edge_value(x, h, b, j, n_in, (long long)n_out);
        }
    }
}

extern "C" void kernel_launch(void* const* d_in, const int* in_sizes, int n_in_arrs,
                              void* d_out, int out_size) {
    const float* x = (const float*)d_in[0];
    const float* h = (const float*)d_in[1];
    const float* b = (const float*)d_in[2];
    float* out = (float*)d_out;

    int n_in = in_sizes[0];  // 8 * 1048576 = 8388608
    long long n3 = (long long)n_in * 3;
    long long n_out = n3 / 2 + ((n3 % 2) ? 1 : 0);  // 12582912
    int out_total = out_size;                        // 12583008
    int nsub = (int)((n_out + GT_OUT - 1) / GT_OUT); // 8192 (= 1536*8192 exactly)

    int grid = nsub / NS;                            // 4096
    fused_kernel<<<grid, BLOCK_T>>>(x, h, b, out, n_in, (int)n_out, out_total, nsub);
}